// round 11
// baseline (speedup 1.0000x reference)
#include <cuda_runtime.h>
#include <cuda_bf16.h>
#include <math.h>
#include <stdint.h>

// Problem constants
#define BATCH 4
#define SEQ   1024
#define CDIM  2048
#define NHEAD 16
#define HDIM  128
#define C3    (3*CDIM)
#define MROWS (BATCH*SEQ)      // 4096
#define BHTOT (BATCH*NHEAD)    // 64
#define KP    4096             // physical K width: [hi(2048) | lo(2048)]
#define NKITER 96              // logical K' = 6144 -> 96 chunks of 64

// ---------------------------------------------------------------------------
// Scratch (__device__ globals; allocation-free rule)
// ---------------------------------------------------------------------------
__device__ float g_cos[SEQ * 64];
__device__ float g_sin[SEQ * 64];
__device__ __nv_bfloat16 g_Abuf[(size_t)MROWS * KP];   // A [hi|lo] [4096][4096]
__device__ __nv_bfloat16 g_Bt1 [(size_t)C3 * KP];      // w_attn^T [hi|lo] [6144][4096]
__device__ __nv_bfloat16 g_Bt2 [(size_t)CDIM * KP];    // w_proj^T [hi|lo] [2048][4096]
// Attention operands, split bf16:
__device__ __nv_bfloat16 g_qs[(size_t)BHTOT * SEQ * 256];  // [bh][t][hi128|lo128] (scaled)
__device__ __nv_bfloat16 g_ks[(size_t)BHTOT * SEQ * 256];  // [bh][t][hi128|lo128]
__device__ __nv_bfloat16 g_vt[(size_t)BHTOT * HDIM * 2 * SEQ]; // [bh][d][hi|lo][t]

// ---------------------------------------------------------------------------
// PTX helpers (arch-neutral: sm_80+ only — NO tcgen05, harness targets compute_103)
// ---------------------------------------------------------------------------
__device__ __forceinline__ uint32_t smem_u32(const void* p) {
    uint32_t a;
    asm("{ .reg .u64 t; cvta.to.shared.u64 t, %1; cvt.u32.u64 %0, t; }" : "=r"(a) : "l"(p));
    return a;
}
#define CP_ASYNC16(dst, src) \
    asm volatile("cp.async.cg.shared.global [%0], [%1], 16;" :: "r"(dst), "l"(src))
#define CP_COMMIT() asm volatile("cp.async.commit_group;" ::: "memory")
#define CP_WAIT(n)  asm volatile("cp.async.wait_group %0;" :: "n"(n) : "memory")

__device__ __forceinline__ void ldsm_x4(uint32_t& r0, uint32_t& r1, uint32_t& r2,
                                        uint32_t& r3, uint32_t addr) {
    asm volatile("ldmatrix.sync.aligned.m8n8.x4.shared.b16 {%0,%1,%2,%3}, [%4];"
                 : "=r"(r0), "=r"(r1), "=r"(r2), "=r"(r3) : "r"(addr));
}
__device__ __forceinline__ void mma_bf16(float& d0, float& d1, float& d2, float& d3,
                                         uint32_t a0, uint32_t a1, uint32_t a2, uint32_t a3,
                                         uint32_t b0, uint32_t b1) {
    asm volatile("mma.sync.aligned.m16n8k16.row.col.f32.bf16.bf16.f32 "
                 "{%0,%1,%2,%3}, {%4,%5,%6,%7}, {%8,%9}, {%0,%1,%2,%3};"
                 : "+f"(d0), "+f"(d1), "+f"(d2), "+f"(d3)
                 : "r"(a0), "r"(a1), "r"(a2), "r"(a3), "r"(b0), "r"(b1));
}
__device__ __forceinline__ uint32_t pack_bf16(float a, float b) {
    __nv_bfloat162 h = __floats2bfloat162_rn(a, b);
    return *(uint32_t*)&h;
}

// ---------------------------------------------------------------------------
// RoPE tables
// ---------------------------------------------------------------------------
__global__ void build_rope_kernel(float* __restrict__ ct, float* __restrict__ st) {
    int idx = blockIdx.x * blockDim.x + threadIdx.x;
    if (idx >= SEQ * 64) return;
    int t = idx >> 6;
    int i = idx & 63;
    double invf = pow(10000.0, -(double)i / 64.0);
    double ang  = (double)t * invf;
    ct[idx] = (float)cos(ang);
    st[idx] = (float)sin(ang);
}

// ---------------------------------------------------------------------------
// Split-bf16 conversion of activations: X fp32 [4096][2048] -> [4096][hi2048|lo2048]
// ---------------------------------------------------------------------------
__global__ void convert_A_kernel(const float* __restrict__ X, __nv_bfloat16* __restrict__ out) {
    int idx = blockIdx.x * blockDim.x + threadIdx.x;
    if (idx >= MROWS * CDIM / 4) return;
    int m  = idx >> 9;
    int c4 = idx & 511;
    float4 v = ((const float4*)X)[idx];
    __nv_bfloat16 h0 = __float2bfloat16(v.x), h1 = __float2bfloat16(v.y);
    __nv_bfloat16 h2 = __float2bfloat16(v.z), h3 = __float2bfloat16(v.w);
    __nv_bfloat16 l0 = __float2bfloat16(v.x - __bfloat162float(h0));
    __nv_bfloat16 l1 = __float2bfloat16(v.y - __bfloat162float(h1));
    __nv_bfloat16 l2 = __float2bfloat16(v.z - __bfloat162float(h2));
    __nv_bfloat16 l3 = __float2bfloat16(v.w - __bfloat162float(h3));
    ushort4 hv = { __bfloat16_as_ushort(h0), __bfloat16_as_ushort(h1),
                   __bfloat16_as_ushort(h2), __bfloat16_as_ushort(h3) };
    ushort4 lv = { __bfloat16_as_ushort(l0), __bfloat16_as_ushort(l1),
                   __bfloat16_as_ushort(l2), __bfloat16_as_ushort(l3) };
    size_t ro = (size_t)m * KP + c4 * 4;
    *(ushort4*)((unsigned short*)out + ro)        = hv;
    *(ushort4*)((unsigned short*)out + ro + CDIM) = lv;
}

// ---------------------------------------------------------------------------
// Split-bf16 + transpose of weights: W fp32 [2048][N] -> out bf16 [N][hi2048|lo2048]
// ---------------------------------------------------------------------------
__global__ void convert_Bt_kernel(const float* __restrict__ W, __nv_bfloat16* __restrict__ out,
                                  int N) {
    __shared__ float t[32][33];
    int k0 = blockIdx.x * 32, n0 = blockIdx.y * 32;
    int tx = threadIdx.x, ty = threadIdx.y;   // (32, 8)
    #pragma unroll
    for (int r = 0; r < 32; r += 8)
        t[ty + r][tx] = W[(size_t)(k0 + ty + r) * N + n0 + tx];
    __syncthreads();
    #pragma unroll
    for (int r = 0; r < 32; r += 8) {
        int n = n0 + ty + r;
        int k = k0 + tx;
        float v = t[tx][ty + r];
        __nv_bfloat16 hi = __float2bfloat16(v);
        __nv_bfloat16 lo = __float2bfloat16(v - __bfloat162float(hi));
        size_t ro = (size_t)n * KP;
        out[ro + k]        = hi;
        out[ro + CDIM + k] = lo;
    }
}

// ---------------------------------------------------------------------------
// mma.sync bf16 GEMM: logical K' = 6144 on [hi|lo] planes
//   (A: [hi|hi|lo], B: [hi|lo|hi]). CTA 128x128, BK=64, 3-stage cp.async ring,
//   4 warps (2Mx2N), warp 64x64. Grid = per-tile (R8 config).
// mode 0: C = acc + bias (fp32) — output projection.
// mode 1: fused QKV epilogue — RoPE + scale + split-bf16 + scatter into
//   qs/ks (t-major) and vt (d-major transpose). No fp32 C write at all.
// ---------------------------------------------------------------------------
#define STAGES 3
#define STAGE_BYTES (32 * 1024)
#define GEMM_SMEM (STAGES * STAGE_BYTES + 1024)
#define EXS 132   // exchange buffer row stride (floats)

__global__ __launch_bounds__(128, 2)
void mma_gemm_kernel(const __nv_bfloat16* __restrict__ A,
                     const __nv_bfloat16* __restrict__ Bt,
                     const float* __restrict__ bias,
                     float* __restrict__ C, int N, int mode,
                     __nv_bfloat16* __restrict__ qs,
                     __nv_bfloat16* __restrict__ ks,
                     __nv_bfloat16* __restrict__ vt,
                     const float* __restrict__ ct,
                     const float* __restrict__ st) {
    extern __shared__ char smem_raw[];
    uint32_t smem_base = (smem_u32(smem_raw) + 1023u) & ~1023u;

    int tid  = threadIdx.x;
    int wid  = tid >> 5, lane = tid & 31;
    int wm   = wid >> 1;          // 0..1 (M: 64 rows each)
    int wn   = wid & 1;           // 0..1 (N: 64 cols each)

    int n0 = blockIdx.x * 128;
    int m0 = blockIdx.y * 128;

    const __nv_bfloat16* Ag0 = A  + (size_t)m0 * KP;
    const __nv_bfloat16* Bg0 = Bt + (size_t)n0 * KP;

    uint32_t a_off[4], a_xor[4];
    #pragma unroll
    for (int mi = 0; mi < 4; mi++) {
        int row = wm * 64 + mi * 16 + (lane & 15);
        a_off[mi] = (uint32_t)row * 128u;
        a_xor[mi] = (uint32_t)((row & 7) << 4);
    }
    uint32_t a_kb = (uint32_t)((lane >> 4) * 16);
    uint32_t b_off[4], b_xor[4];
    #pragma unroll
    for (int ng = 0; ng < 4; ng++) {
        int row = wn * 64 + ng * 16 + ((lane >> 4) << 3) + (lane & 7);
        b_off[ng] = 16384u + (uint32_t)row * 128u;
        b_xor[ng] = (uint32_t)((row & 7) << 4);
    }
    uint32_t b_kb = (uint32_t)(((lane >> 3) & 1) * 16);

    float d[4][8][4];
    #pragma unroll
    for (int mi = 0; mi < 4; mi++)
        #pragma unroll
        for (int ni = 0; ni < 8; ni++)
            #pragma unroll
            for (int c = 0; c < 4; c++) d[mi][ni][c] = 0.f;

    auto fill = [&](int s, int i) {
        int ia = (i < 32) ? i : i - 32;   // A physical chunk ([hi|hi|lo])
        int ib = (i < 64) ? i : i - 64;   // B physical chunk ([hi|lo|hi])
        uint32_t st_base = smem_base + s * STAGE_BYTES;
        const __nv_bfloat16* Ag = Ag0 + ia * 64;
        #pragma unroll
        for (int j = 0; j < 8; j++) {
            int ch  = j * 128 + tid;              // 0..1023
            int row = ch >> 3, col = ch & 7;
            uint32_t off = (uint32_t)row * 128u + (uint32_t)col * 16u;
            uint32_t dst = st_base + (off ^ ((off >> 3) & 0x70u));
            CP_ASYNC16(dst, Ag + (size_t)row * KP + col * 8);
        }
        const __nv_bfloat16* Bg = Bg0 + ib * 64;
        #pragma unroll
        for (int j = 0; j < 8; j++) {
            int ch  = j * 128 + tid;
            int row = ch >> 3, col = ch & 7;
            uint32_t off = (uint32_t)row * 128u + (uint32_t)col * 16u;
            uint32_t dst = st_base + 16384u + (off ^ ((off >> 3) & 0x70u));
            CP_ASYNC16(dst, Bg + (size_t)row * KP + col * 8);
        }
    };

    fill(0, 0); CP_COMMIT();
    fill(1, 1); CP_COMMIT();

    for (int i = 0; i < NKITER; i++) {
        int s = i % STAGES;
        CP_WAIT(1);
        __syncthreads();
        if (i + 2 < NKITER) fill((i + 2) % STAGES, i + 2);
        CP_COMMIT();

        uint32_t stb = smem_base + s * STAGE_BYTES;
        #pragma unroll
        for (int ks2 = 0; ks2 < 4; ks2++) {
            uint32_t kk = (uint32_t)(ks2 * 32);
            uint32_t af[4][4];
            #pragma unroll
            for (int mi = 0; mi < 4; mi++) {
                uint32_t addr = stb + a_off[mi] + ((kk + a_kb) ^ a_xor[mi]);
                ldsm_x4(af[mi][0], af[mi][1], af[mi][2], af[mi][3], addr);
            }
            uint32_t bf[4][4];
            #pragma unroll
            for (int ng = 0; ng < 4; ng++) {
                uint32_t addr = stb + b_off[ng] + ((kk + b_kb) ^ b_xor[ng]);
                ldsm_x4(bf[ng][0], bf[ng][1], bf[ng][2], bf[ng][3], addr);
            }
            #pragma unroll
            for (int mi = 0; mi < 4; mi++)
                #pragma unroll
                for (int ni = 0; ni < 8; ni++) {
                    int ng = ni >> 1, sub = ni & 1;
                    mma_bf16(d[mi][ni][0], d[mi][ni][1], d[mi][ni][2], d[mi][ni][3],
                             af[mi][0], af[mi][1], af[mi][2], af[mi][3],
                             bf[ng][sub * 2], bf[ng][sub * 2 + 1]);
                }
        }
    }
    CP_WAIT(0);

    int row_base = wm * 64 + (lane >> 2);         // CTA-local row
    int col_base = wn * 64 + (lane & 3) * 2;      // CTA-local col

    if (mode == 0) {
        // plain epilogue: C = acc + bias (fp32)
        #pragma unroll
        for (int ni = 0; ni < 8; ni++) {
            int col = n0 + col_base + ni * 8;
            float2 bs = *(const float2*)(bias + col);
            #pragma unroll
            for (int mi = 0; mi < 4; mi++) {
                int r0 = m0 + row_base + mi * 16;
                float2 v0 = { d[mi][ni][0] + bs.x, d[mi][ni][1] + bs.y };
                float2 v1 = { d[mi][ni][2] + bs.x, d[mi][ni][3] + bs.y };
                *(float2*)(C + (size_t)r0 * N + col)       = v0;
                *(float2*)(C + (size_t)(r0 + 8) * N + col) = v1;
            }
        }
        return;
    }

    // ---- mode 1: fused QKV epilogue ----
    // Stage tile (with bias) into smem exchange buffer (RoPE partner d^64 is
    // owned by the other wn-warp).
    float* ex = (float*)smem_raw;
    __syncthreads();   // all mma reads of stage smem done before overwrite
    #pragma unroll
    for (int ni = 0; ni < 8; ni++) {
        int col = col_base + ni * 8;
        float2 bs = *(const float2*)(bias + n0 + col);
        #pragma unroll
        for (int mi = 0; mi < 4; mi++) {
            int r0 = row_base + mi * 16;
            ex[(r0    ) * EXS + col    ] = d[mi][ni][0] + bs.x;
            ex[(r0    ) * EXS + col + 1] = d[mi][ni][1] + bs.y;
            ex[(r0 + 8) * EXS + col    ] = d[mi][ni][2] + bs.x;
            ex[(r0 + 8) * EXS + col + 1] = d[mi][ni][3] + bs.y;
        }
    }
    __syncthreads();

    int sect = n0 >> 11;              // 0=q, 1=k, 2=v
    int h    = (n0 >> 7) & 15;        // head (128-wide tiles align to heads)
    int b    = m0 >> 10;
    int bh   = b * NHEAD + h;
    int t0   = m0 & 1023;

    #pragma unroll
    for (int mi = 0; mi < 4; mi++) {
        #pragma unroll
        for (int c2 = 0; c2 < 2; c2++) {
            int r = row_base + mi * 16 + c2 * 8;
            int t = t0 + r;
            #pragma unroll
            for (int ni = 0; ni < 8; ni++) {
                int dl = col_base + ni * 8;       // even; handles dl, dl+1
                float o0, o1;
                if (sect == 2) {
                    o0 = ex[r * EXS + dl];
                    o1 = ex[r * EXS + dl + 1];
                } else {
                    int i0 = dl & 63;
                    float own0 = ex[r * EXS + dl];
                    float own1 = ex[r * EXS + dl + 1];
                    float par0 = ex[r * EXS + (dl ^ 64)];
                    float par1 = ex[r * EXS + ((dl + 1) ^ 64)];
                    float c0 = ct[t * 64 + i0],     s0 = st[t * 64 + i0];
                    float c1 = ct[t * 64 + i0 + 1], s1 = st[t * 64 + i0 + 1];
                    if (dl < 64) { o0 = own0 * c0 - par0 * s0; o1 = own1 * c1 - par1 * s1; }
                    else         { o0 = own0 * c0 + par0 * s0; o1 = own1 * c1 + par1 * s1; }
                    if (sect == 0) {
                        const float scale = 0.08838834764831845f;  // 1/sqrt(128)
                        o0 *= scale; o1 *= scale;
                    }
                }
                __nv_bfloat16 h0 = __float2bfloat16(o0);
                __nv_bfloat16 h1 = __float2bfloat16(o1);
                float l0 = o0 - __bfloat162float(h0);
                float l1 = o1 - __bfloat162float(h1);
                if (sect == 2) {
                    // vt [bh][d][hi|lo][t]
                    size_t base0 = (((size_t)bh * HDIM + dl    ) * 2) * SEQ + t;
                    size_t base1 = (((size_t)bh * HDIM + dl + 1) * 2) * SEQ + t;
                    vt[base0]       = h0;
                    vt[base0 + SEQ] = __float2bfloat16(l0);
                    vt[base1]       = h1;
                    vt[base1 + SEQ] = __float2bfloat16(l1);
                } else {
                    __nv_bfloat16* dstp = (sect == 0) ? qs : ks;
                    size_t ro = ((size_t)bh * SEQ + t) * 256;
                    *(uint32_t*)(dstp + ro + dl)       = pack_bf16(__bfloat162float(h0),
                                                                    __bfloat162float(h1));
                    *(uint32_t*)(dstp + ro + 128 + dl) = pack_bf16(l0, l1);
                }
            }
        }
    }
}

// ---------------------------------------------------------------------------
// Tensor-core flash attention, split-bf16, causal.
// CTA: 64 q rows (one bh), 4 warps x 16 rows x full 32-col k-tile.
// Epilogue writes split-bf16 straight into Abuf [hi|lo] for the proj GEMM.
// ---------------------------------------------------------------------------
#define FA_SMEM (32768 + 2 * 32768 + 128)

__global__ __launch_bounds__(128, 2)
void flash_mma_kernel(const __nv_bfloat16* __restrict__ qs,
                      const __nv_bfloat16* __restrict__ ks,
                      const __nv_bfloat16* __restrict__ vt,
                      __nv_bfloat16* __restrict__ Ab) {
    extern __shared__ char smraw[];
    uint32_t smQ = (smem_u32(smraw) + 127u) & ~127u;

    int tid  = threadIdx.x;
    int wid  = tid >> 5, lane = tid & 31;
    int qt   = gridDim.x - 1 - blockIdx.x;   // heavy first
    int bh   = blockIdx.y;
    int q0   = qt * 64;
    int b = bh >> 4, h = bh & 15;

    const __nv_bfloat16* Qg = qs + ((size_t)bh * SEQ + q0) * 256;
    #pragma unroll
    for (int j = 0; j < 16; j++) {
        int ch = j * 128 + tid;
        int row = ch >> 5, c16 = ch & 31;
        uint32_t dst = smQ + (uint32_t)row * 512u + (uint32_t)((c16 ^ (row & 7)) << 4);
        CP_ASYNC16(dst, Qg + (size_t)row * 256 + c16 * 8);
    }

    auto fillKV = [&](int s, int kt) {
        int k0 = kt * 32;
        uint32_t smK = smQ + 32768u + (uint32_t)s * 32768u;
        uint32_t smV = smK + 16384u;
        const __nv_bfloat16* Kg = ks + ((size_t)bh * SEQ + k0) * 256;
        #pragma unroll
        for (int j = 0; j < 8; j++) {
            int ch = j * 128 + tid;
            int row = ch >> 5, c16 = ch & 31;
            uint32_t dst = smK + (uint32_t)row * 512u + (uint32_t)((c16 ^ (row & 7)) << 4);
            CP_ASYNC16(dst, Kg + (size_t)row * 256 + c16 * 8);
        }
        const __nv_bfloat16* Vg = vt + (size_t)bh * HDIM * 2 * SEQ + k0;
        #pragma unroll
        for (int j = 0; j < 8; j++) {
            int ch = j * 128 + tid;
            int row = ch >> 3, c16 = ch & 7;
            int plane = c16 >> 2, tc = c16 & 3;
            uint32_t dst = smV + (uint32_t)row * 128u + (uint32_t)((c16 ^ (row & 7)) << 4);
            CP_ASYNC16(dst, Vg + ((size_t)row * 2 + plane) * SEQ + tc * 8);
        }
    };

    fillKV(0, 0);
    CP_COMMIT();

    float O[16][4];
    #pragma unroll
    for (int nf = 0; nf < 16; nf++)
        #pragma unroll
        for (int c = 0; c < 4; c++) O[nf][c] = 0.f;
    float mrow[2] = { -1e30f, -1e30f };
    float lrow[2] = { 0.f, 0.f };

    int arow = wid * 16 + (lane & 15);
    uint32_t a_base = (uint32_t)arow * 512u;
    uint32_t a_x7   = (uint32_t)(arow & 7) << 4;
    uint32_t a_kb   = (uint32_t)((lane >> 4) << 4);
    int b_sub = ((lane >> 4) << 3) + (lane & 7);
    uint32_t b_kb = (uint32_t)(((lane >> 3) & 1) << 4);

    int nkt = 2 * qt + 2;
    for (int kt = 0; kt < nkt; kt++) {
        if (kt + 1 < nkt) { fillKV((kt + 1) & 1, kt + 1); CP_COMMIT(); CP_WAIT(1); }
        else              { CP_WAIT(0); }
        __syncthreads();

        uint32_t smK = smQ + 32768u + (uint32_t)(kt & 1) * 32768u;
        uint32_t smV = smK + 16384u;

        float S[4][4];
        #pragma unroll
        for (int ni = 0; ni < 4; ni++)
            #pragma unroll
            for (int c = 0; c < 4; c++) S[ni][c] = 0.f;

        #pragma unroll
        for (int p = 0; p < 3; p++) {
            uint32_t qoff = (p == 2) ? 256u : 0u;
            uint32_t koff = (p == 1) ? 256u : 0u;
            #pragma unroll
            for (int kd = 0; kd < 8; kd++) {
                uint32_t a[4];
                ldsm_x4(a[0], a[1], a[2], a[3],
                        smQ + a_base + ((qoff + kd * 32 + a_kb) ^ a_x7));
                #pragma unroll
                for (int g = 0; g < 2; g++) {
                    int brow = g * 16 + b_sub;
                    uint32_t bf[4];
                    ldsm_x4(bf[0], bf[1], bf[2], bf[3],
                            smK + (uint32_t)brow * 512u +
                            ((koff + kd * 32 + b_kb) ^ ((uint32_t)(brow & 7) << 4)));
                    #pragma unroll
                    for (int sub = 0; sub < 2; sub++)
                        mma_bf16(S[g*2+sub][0], S[g*2+sub][1], S[g*2+sub][2], S[g*2+sub][3],
                                 a[0], a[1], a[2], a[3], bf[sub*2], bf[sub*2+1]);
                }
            }
        }

        if (kt >= 2 * qt) {
            int k0 = kt * 32;
            #pragma unroll
            for (int ni = 0; ni < 4; ni++) {
                #pragma unroll
                for (int c = 0; c < 4; c++) {
                    int gr = q0 + wid * 16 + (lane >> 2) + ((c >> 1) << 3);
                    int gc = k0 + ni * 8 + (lane & 3) * 2 + (c & 1);
                    if (gc > gr) S[ni][c] = -1e30f;
                }
            }
        }

        uint32_t phi[2][4], plo[2][4];
        #pragma unroll
        for (int i = 0; i < 2; i++) {
            float vmax = -1e30f;
            #pragma unroll
            for (int ni = 0; ni < 4; ni++)
                vmax = fmaxf(vmax, fmaxf(S[ni][2*i], S[ni][2*i+1]));
            vmax = fmaxf(vmax, __shfl_xor_sync(0xffffffffu, vmax, 1));
            vmax = fmaxf(vmax, __shfl_xor_sync(0xffffffffu, vmax, 2));
            float mnew  = fmaxf(mrow[i], vmax);
            float alpha = __expf(mrow[i] - mnew);
            mrow[i] = mnew;
            float rs = 0.f;
            #pragma unroll
            for (int ni = 0; ni < 4; ni++) {
                float p0 = __expf(S[ni][2*i]   - mnew);
                float p1 = __expf(S[ni][2*i+1] - mnew);
                S[ni][2*i] = p0; S[ni][2*i+1] = p1;
                rs += p0 + p1;
            }
            rs += __shfl_xor_sync(0xffffffffu, rs, 1);
            rs += __shfl_xor_sync(0xffffffffu, rs, 2);
            lrow[i] = lrow[i] * alpha + rs;
            #pragma unroll
            for (int nf = 0; nf < 16; nf++) {
                O[nf][2*i]   *= alpha;
                O[nf][2*i+1] *= alpha;
            }
        }
        #pragma unroll
        for (int ks2 = 0; ks2 < 2; ks2++) {
            #pragma unroll
            for (int half = 0; half < 2; half++) {
                int ni = 2 * ks2 + half;
                float p00 = S[ni][0], p01 = S[ni][1], p10 = S[ni][2], p11 = S[ni][3];
                __nv_bfloat16 h00 = __float2bfloat16(p00), h01 = __float2bfloat16(p01);
                __nv_bfloat16 h10 = __float2bfloat16(p10), h11 = __float2bfloat16(p11);
                phi[ks2][half*2+0] = pack_bf16(__bfloat162float(h00), __bfloat162float(h01));
                phi[ks2][half*2+1] = pack_bf16(__bfloat162float(h10), __bfloat162float(h11));
                plo[ks2][half*2+0] = pack_bf16(p00 - __bfloat162float(h00),
                                               p01 - __bfloat162float(h01));
                plo[ks2][half*2+1] = pack_bf16(p10 - __bfloat162float(h10),
                                               p11 - __bfloat162float(h11));
            }
        }

        #pragma unroll
        for (int p = 0; p < 3; p++) {
            uint32_t (*A)[4] = (p == 2) ? plo : phi;
            uint32_t voff = (p == 1) ? 64u : 0u;
            #pragma unroll
            for (int ks2 = 0; ks2 < 2; ks2++) {
                uint32_t koffb = voff + ks2 * 32;
                #pragma unroll
                for (int nb = 0; nb < 8; nb++) {
                    int brow = nb * 16 + b_sub;
                    uint32_t bv[4];
                    ldsm_x4(bv[0], bv[1], bv[2], bv[3],
                            smV + (uint32_t)brow * 128u +
                            ((koffb + b_kb) ^ ((uint32_t)(brow & 7) << 4)));
                    #pragma unroll
                    for (int sub = 0; sub < 2; sub++) {
                        int nf = nb * 2 + sub;
                        mma_bf16(O[nf][0], O[nf][1], O[nf][2], O[nf][3],
                                 A[ks2][0], A[ks2][1], A[ks2][2], A[ks2][3],
                                 bv[sub*2], bv[sub*2+1]);
                    }
                }
            }
        }
        __syncthreads();
    }

    // ---- epilogue: normalize + split-bf16 straight into Abuf [hi|lo] ----
    #pragma unroll
    for (int i = 0; i < 2; i++) {
        float inv = 1.0f / lrow[i];
        int trow = q0 + wid * 16 + (lane >> 2) + 8 * i;
        size_t mrowg = (size_t)(b * SEQ + trow) * KP;
        int cbase = h * HDIM + (lane & 3) * 2;
        #pragma unroll
        for (int nf = 0; nf < 16; nf++) {
            float o0 = O[nf][2*i]   * inv;
            float o1 = O[nf][2*i+1] * inv;
            __nv_bfloat16 h0 = __float2bfloat16(o0);
            __nv_bfloat16 h1 = __float2bfloat16(o1);
            int col = cbase + nf * 8;
            *(uint32_t*)(Ab + mrowg + col) =
                pack_bf16(__bfloat162float(h0), __bfloat162float(h1));
            *(uint32_t*)(Ab + mrowg + CDIM + col) =
                pack_bf16(o0 - __bfloat162float(h0), o1 - __bfloat162float(h1));
        }
    }
}

// ---------------------------------------------------------------------------
extern "C" void kernel_launch(void* const* d_in, const int* in_sizes, int n_in,
                              void* d_out, int out_size) {
    const float* x      = (const float*)d_in[0];
    const float* w_attn = (const float*)d_in[1];
    const float* b_attn = (const float*)d_in[2];
    const float* w_proj = (const float*)d_in[3];
    const float* b_proj = (const float*)d_in[4];
    float* out = (float*)d_out;

    float *ct, *st;
    __nv_bfloat16 *Abuf, *Bt1, *Bt2, *qsb, *ksb, *vtb;
    cudaGetSymbolAddress((void**)&ct,   g_cos);
    cudaGetSymbolAddress((void**)&st,   g_sin);
    cudaGetSymbolAddress((void**)&Abuf, g_Abuf);
    cudaGetSymbolAddress((void**)&Bt1,  g_Bt1);
    cudaGetSymbolAddress((void**)&Bt2,  g_Bt2);
    cudaGetSymbolAddress((void**)&qsb,  g_qs);
    cudaGetSymbolAddress((void**)&ksb,  g_ks);
    cudaGetSymbolAddress((void**)&vtb,  g_vt);

    cudaFuncSetAttribute(mma_gemm_kernel,
                         cudaFuncAttributeMaxDynamicSharedMemorySize, GEMM_SMEM);
    cudaFuncSetAttribute(flash_mma_kernel,
                         cudaFuncAttributeMaxDynamicSharedMemorySize, FA_SMEM);

    // RoPE tables
    build_rope_kernel<<<(SEQ * 64 + 255) / 256, 256>>>(ct, st);

    // Split-bf16 conversions for QKV GEMM
    convert_A_kernel<<<(MROWS * CDIM / 4 + 255) / 256, 256>>>(x, Abuf);
    convert_Bt_kernel<<<dim3(CDIM / 32, C3 / 32), dim3(32, 8)>>>(w_attn, Bt1, C3);

    // QKV projection (HMMA) with fused RoPE/split/scatter epilogue
    mma_gemm_kernel<<<dim3(C3 / 128, MROWS / 128), 128, GEMM_SMEM>>>(
        Abuf, Bt1, b_attn, nullptr, C3, 1, qsb, ksb, vtb, ct, st);

    // Tensor-core flash attention -> Abuf [hi|lo] (fused conversion)
    flash_mma_kernel<<<dim3(SEQ / 64, BHTOT), 128, FA_SMEM>>>(qsb, ksb, vtb, Abuf);

    // Split-bf16 conversion for output projection weights
    convert_Bt_kernel<<<dim3(CDIM / 32, CDIM / 32), dim3(32, 8)>>>(w_proj, Bt2, CDIM);

    // Output projection (HMMA) -> d_out
    mma_gemm_kernel<<<dim3(CDIM / 128, MROWS / 128), 128, GEMM_SMEM>>>(
        Abuf, Bt2, b_proj, out, CDIM, 0, nullptr, nullptr, nullptr, nullptr, nullptr);
}

// round 14
// speedup vs baseline: 1.5545x; 1.5545x over previous
#include <cuda_runtime.h>
#include <cuda_bf16.h>
#include <math.h>
#include <stdint.h>

// Problem constants
#define BATCH 4
#define SEQ   1024
#define CDIM  2048
#define NHEAD 16
#define HDIM  128
#define C3    (3*CDIM)
#define MROWS (BATCH*SEQ)      // 4096
#define BHTOT (BATCH*NHEAD)    // 64
#define KP    4096             // physical K width: [hi(2048) | lo(2048)]
#define NKITER 96              // logical K' = 6144 -> 96 chunks of 64

// ---------------------------------------------------------------------------
// Scratch (__device__ globals; allocation-free rule)
// ---------------------------------------------------------------------------
__device__ float g_qkv[(size_t)MROWS * C3];
__device__ float g_y  [(size_t)MROWS * CDIM];
__device__ float g_cos[SEQ * 64];
__device__ float g_sin[SEQ * 64];
__device__ __nv_bfloat16 g_Abuf[(size_t)MROWS * KP];   // A [hi|lo] [4096][4096]
__device__ __nv_bfloat16 g_Bt1 [(size_t)C3 * KP];      // w_attn^T [hi|lo] [6144][4096]
__device__ __nv_bfloat16 g_Bt2 [(size_t)CDIM * KP];    // w_proj^T [hi|lo] [2048][4096]
// Attention operands, split bf16:
__device__ __nv_bfloat16 g_qs[(size_t)BHTOT * SEQ * 256];  // [bh][t][hi128|lo128] (scaled)
__device__ __nv_bfloat16 g_ks[(size_t)BHTOT * SEQ * 256];  // [bh][t][hi128|lo128]
__device__ __nv_bfloat16 g_vt[(size_t)BHTOT * HDIM * 2 * SEQ]; // [bh][d][hi|lo][t]

// ---------------------------------------------------------------------------
// PTX helpers (arch-neutral: sm_80+ only — NO tcgen05, harness targets compute_103)
// ---------------------------------------------------------------------------
__device__ __forceinline__ uint32_t smem_u32(const void* p) {
    uint32_t a;
    asm("{ .reg .u64 t; cvta.to.shared.u64 t, %1; cvt.u32.u64 %0, t; }" : "=r"(a) : "l"(p));
    return a;
}
#define CP_ASYNC16(dst, src) \
    asm volatile("cp.async.cg.shared.global [%0], [%1], 16;" :: "r"(dst), "l"(src))
#define CP_COMMIT() asm volatile("cp.async.commit_group;" ::: "memory")
#define CP_WAIT(n)  asm volatile("cp.async.wait_group %0;" :: "n"(n) : "memory")

__device__ __forceinline__ void ldsm_x4(uint32_t& r0, uint32_t& r1, uint32_t& r2,
                                        uint32_t& r3, uint32_t addr) {
    asm volatile("ldmatrix.sync.aligned.m8n8.x4.shared.b16 {%0,%1,%2,%3}, [%4];"
                 : "=r"(r0), "=r"(r1), "=r"(r2), "=r"(r3) : "r"(addr));
}
__device__ __forceinline__ void mma_bf16(float& d0, float& d1, float& d2, float& d3,
                                         uint32_t a0, uint32_t a1, uint32_t a2, uint32_t a3,
                                         uint32_t b0, uint32_t b1) {
    asm volatile("mma.sync.aligned.m16n8k16.row.col.f32.bf16.bf16.f32 "
                 "{%0,%1,%2,%3}, {%4,%5,%6,%7}, {%8,%9}, {%0,%1,%2,%3};"
                 : "+f"(d0), "+f"(d1), "+f"(d2), "+f"(d3)
                 : "r"(a0), "r"(a1), "r"(a2), "r"(a3), "r"(b0), "r"(b1));
}
__device__ __forceinline__ uint32_t pack_bf16(float a, float b) {
    __nv_bfloat162 h = __floats2bfloat162_rn(a, b);
    return *(uint32_t*)&h;
}

// ---------------------------------------------------------------------------
// RoPE tables
// ---------------------------------------------------------------------------
__global__ void build_rope_kernel(float* __restrict__ ct, float* __restrict__ st) {
    int idx = blockIdx.x * blockDim.x + threadIdx.x;
    if (idx >= SEQ * 64) return;
    int t = idx >> 6;
    int i = idx & 63;
    double invf = pow(10000.0, -(double)i / 64.0);
    double ang  = (double)t * invf;
    ct[idx] = (float)cos(ang);
    st[idx] = (float)sin(ang);
}

// ---------------------------------------------------------------------------
// Split-bf16 conversion of activations: X fp32 [4096][2048] -> [4096][hi2048|lo2048]
// ---------------------------------------------------------------------------
__global__ void convert_A_kernel(const float* __restrict__ X, __nv_bfloat16* __restrict__ out) {
    int idx = blockIdx.x * blockDim.x + threadIdx.x;
    if (idx >= MROWS * CDIM / 4) return;
    int m  = idx >> 9;
    int c4 = idx & 511;
    float4 v = ((const float4*)X)[idx];
    __nv_bfloat16 h0 = __float2bfloat16(v.x), h1 = __float2bfloat16(v.y);
    __nv_bfloat16 h2 = __float2bfloat16(v.z), h3 = __float2bfloat16(v.w);
    __nv_bfloat16 l0 = __float2bfloat16(v.x - __bfloat162float(h0));
    __nv_bfloat16 l1 = __float2bfloat16(v.y - __bfloat162float(h1));
    __nv_bfloat16 l2 = __float2bfloat16(v.z - __bfloat162float(h2));
    __nv_bfloat16 l3 = __float2bfloat16(v.w - __bfloat162float(h3));
    ushort4 hv = { __bfloat16_as_ushort(h0), __bfloat16_as_ushort(h1),
                   __bfloat16_as_ushort(h2), __bfloat16_as_ushort(h3) };
    ushort4 lv = { __bfloat16_as_ushort(l0), __bfloat16_as_ushort(l1),
                   __bfloat16_as_ushort(l2), __bfloat16_as_ushort(l3) };
    size_t ro = (size_t)m * KP + c4 * 4;
    *(ushort4*)((unsigned short*)out + ro)        = hv;
    *(ushort4*)((unsigned short*)out + ro + CDIM) = lv;
}

// ---------------------------------------------------------------------------
// Split-bf16 + transpose of weights: W fp32 [2048][N] -> out bf16 [N][hi2048|lo2048]
// ---------------------------------------------------------------------------
__global__ void convert_Bt_kernel(const float* __restrict__ W, __nv_bfloat16* __restrict__ out,
                                  int N) {
    __shared__ float t[32][33];
    int k0 = blockIdx.x * 32, n0 = blockIdx.y * 32;
    int tx = threadIdx.x, ty = threadIdx.y;   // (32, 8)
    #pragma unroll
    for (int r = 0; r < 32; r += 8)
        t[ty + r][tx] = W[(size_t)(k0 + ty + r) * N + n0 + tx];
    __syncthreads();
    #pragma unroll
    for (int r = 0; r < 32; r += 8) {
        int n = n0 + ty + r;
        int k = k0 + tx;
        float v = t[tx][ty + r];
        __nv_bfloat16 hi = __float2bfloat16(v);
        __nv_bfloat16 lo = __float2bfloat16(v - __bfloat162float(hi));
        size_t ro = (size_t)n * KP;
        out[ro + k]        = hi;
        out[ro + CDIM + k] = lo;
    }
}

// ---------------------------------------------------------------------------
// mma.sync bf16 GEMM (R9 champion config): C = A''@Bt''^T + bias
// logical K' = 6144 on [hi|lo] planes (A: [hi|hi|lo], B: [hi|lo|hi]).
// CTA tile 128x128, BK=64, 3-stage cp.async ring, 4 warps (2Mx2N), warp 64x64.
// ---------------------------------------------------------------------------
#define STAGES 3
#define STAGE_BYTES (32 * 1024)
#define GEMM_SMEM (STAGES * STAGE_BYTES + 1024)

__global__ __launch_bounds__(128, 2)
void mma_gemm_kernel(const __nv_bfloat16* __restrict__ A,
                     const __nv_bfloat16* __restrict__ Bt,
                     const float* __restrict__ bias,
                     float* __restrict__ C, int N) {
    extern __shared__ char smem_raw[];
    uint32_t smem_base = (smem_u32(smem_raw) + 1023u) & ~1023u;

    int tid  = threadIdx.x;
    int wid  = tid >> 5, lane = tid & 31;
    int wm   = wid >> 1;          // 0..1 (M: 64 rows each)
    int wn   = wid & 1;           // 0..1 (N: 64 cols each)

    int n0 = blockIdx.x * 128;
    int m0 = blockIdx.y * 128;

    const __nv_bfloat16* Ag0 = A  + (size_t)m0 * KP;
    const __nv_bfloat16* Bg0 = Bt + (size_t)n0 * KP;

    uint32_t a_off[4], a_xor[4];
    #pragma unroll
    for (int mi = 0; mi < 4; mi++) {
        int row = wm * 64 + mi * 16 + (lane & 15);
        a_off[mi] = (uint32_t)row * 128u;
        a_xor[mi] = (uint32_t)((row & 7) << 4);
    }
    uint32_t a_kb = (uint32_t)((lane >> 4) * 16);
    uint32_t b_off[4], b_xor[4];
    #pragma unroll
    for (int ng = 0; ng < 4; ng++) {
        int row = wn * 64 + ng * 16 + ((lane >> 4) << 3) + (lane & 7);
        b_off[ng] = 16384u + (uint32_t)row * 128u;
        b_xor[ng] = (uint32_t)((row & 7) << 4);
    }
    uint32_t b_kb = (uint32_t)(((lane >> 3) & 1) * 16);

    float d[4][8][4];
    #pragma unroll
    for (int mi = 0; mi < 4; mi++)
        #pragma unroll
        for (int ni = 0; ni < 8; ni++)
            #pragma unroll
            for (int c = 0; c < 4; c++) d[mi][ni][c] = 0.f;

    auto fill = [&](int s, int i) {
        int ia = (i < 32) ? i : i - 32;   // A physical chunk ([hi|hi|lo])
        int ib = (i < 64) ? i : i - 64;   // B physical chunk ([hi|lo|hi])
        uint32_t st_base = smem_base + s * STAGE_BYTES;
        const __nv_bfloat16* Ag = Ag0 + ia * 64;
        #pragma unroll
        for (int j = 0; j < 8; j++) {
            int ch  = j * 128 + tid;              // 0..1023
            int row = ch >> 3, col = ch & 7;
            uint32_t off = (uint32_t)row * 128u + (uint32_t)col * 16u;
            uint32_t dst = st_base + (off ^ ((off >> 3) & 0x70u));
            CP_ASYNC16(dst, Ag + (size_t)row * KP + col * 8);
        }
        const __nv_bfloat16* Bg = Bg0 + ib * 64;
        #pragma unroll
        for (int j = 0; j < 8; j++) {
            int ch  = j * 128 + tid;
            int row = ch >> 3, col = ch & 7;
            uint32_t off = (uint32_t)row * 128u + (uint32_t)col * 16u;
            uint32_t dst = st_base + 16384u + (off ^ ((off >> 3) & 0x70u));
            CP_ASYNC16(dst, Bg + (size_t)row * KP + col * 8);
        }
    };

    fill(0, 0); CP_COMMIT();
    fill(1, 1); CP_COMMIT();

    for (int i = 0; i < NKITER; i++) {
        int s = i % STAGES;
        CP_WAIT(1);
        __syncthreads();
        if (i + 2 < NKITER) fill((i + 2) % STAGES, i + 2);
        CP_COMMIT();

        uint32_t stb = smem_base + s * STAGE_BYTES;
        #pragma unroll
        for (int ks = 0; ks < 4; ks++) {
            uint32_t kk = (uint32_t)(ks * 32);
            uint32_t af[4][4];
            #pragma unroll
            for (int mi = 0; mi < 4; mi++) {
                uint32_t addr = stb + a_off[mi] + ((kk + a_kb) ^ a_xor[mi]);
                ldsm_x4(af[mi][0], af[mi][1], af[mi][2], af[mi][3], addr);
            }
            uint32_t bf[4][4];
            #pragma unroll
            for (int ng = 0; ng < 4; ng++) {
                uint32_t addr = stb + b_off[ng] + ((kk + b_kb) ^ b_xor[ng]);
                ldsm_x4(bf[ng][0], bf[ng][1], bf[ng][2], bf[ng][3], addr);
            }
            #pragma unroll
            for (int mi = 0; mi < 4; mi++)
                #pragma unroll
                for (int ni = 0; ni < 8; ni++) {
                    int ng = ni >> 1, sub = ni & 1;
                    mma_bf16(d[mi][ni][0], d[mi][ni][1], d[mi][ni][2], d[mi][ni][3],
                             af[mi][0], af[mi][1], af[mi][2], af[mi][3],
                             bf[ng][sub * 2], bf[ng][sub * 2 + 1]);
                }
        }
    }
    CP_WAIT(0);

    int row_base = m0 + wm * 64 + (lane >> 2);
    int col_base = n0 + wn * 64 + (lane & 3) * 2;
    #pragma unroll
    for (int ni = 0; ni < 8; ni++) {
        int col = col_base + ni * 8;
        float2 bs = *(const float2*)(bias + col);
        #pragma unroll
        for (int mi = 0; mi < 4; mi++) {
            int r0 = row_base + mi * 16;
            float2 v0 = { d[mi][ni][0] + bs.x, d[mi][ni][1] + bs.y };
            float2 v1 = { d[mi][ni][2] + bs.x, d[mi][ni][3] + bs.y };
            *(float2*)(C + (size_t)r0 * N + col)       = v0;
            *(float2*)(C + (size_t)(r0 + 8) * N + col) = v1;
        }
    }
}

// ---------------------------------------------------------------------------
// RoPE + split into bf16 hi/lo: qkv -> g_qs (scaled), g_ks  [bh][t][hi128|lo128]
// ---------------------------------------------------------------------------
__global__ void rope_split_kernel(const float* __restrict__ qkv,
                                  const float* __restrict__ ct,
                                  const float* __restrict__ st,
                                  __nv_bfloat16* __restrict__ qs,
                                  __nv_bfloat16* __restrict__ ks) {
    int idx = blockIdx.x * blockDim.x + threadIdx.x;
    if (idx >= BHTOT * SEQ * HDIM) return;
    int d  = idx & 127;
    int t  = (idx >> 7) & 1023;
    int bh = idx >> 17;
    int b  = bh >> 4;
    int h  = bh & 15;
    const float scale = 0.08838834764831845f;  // 1/sqrt(128)

    size_t base = (size_t)(b * SEQ + t) * C3 + h * HDIM;
    int i = d & 63;
    float c = ct[t * 64 + i];
    float s = st[t * 64 + i];
    float q1 = qkv[base + i];
    float q2 = qkv[base + i + 64];
    float k1 = qkv[base + CDIM + i];
    float k2 = qkv[base + CDIM + i + 64];
    float qo, ko;
    if (d < 64) { qo = q1 * c - q2 * s; ko = k1 * c - k2 * s; }
    else        { qo = q1 * s + q2 * c; ko = k1 * s + k2 * c; }
    qo *= scale;

    __nv_bfloat16 qh = __float2bfloat16(qo);
    __nv_bfloat16 ql = __float2bfloat16(qo - __bfloat162float(qh));
    __nv_bfloat16 kh = __float2bfloat16(ko);
    __nv_bfloat16 kl = __float2bfloat16(ko - __bfloat162float(kh));
    size_t ro = ((size_t)bh * SEQ + t) * 256;
    qs[ro + d]       = qh;
    qs[ro + 128 + d] = ql;
    ks[ro + d]       = kh;
    ks[ro + 128 + d] = kl;
}

// ---------------------------------------------------------------------------
// V transpose + split: qkv v-part [b][t][h][d] -> g_vt [bh][d][hi|lo][t]
// ---------------------------------------------------------------------------
__global__ void vt_split_kernel(const float* __restrict__ qkv,
                                __nv_bfloat16* __restrict__ vt) {
    __shared__ float tile[32][33];
    int t0 = blockIdx.x * 32;
    int d0 = blockIdx.y * 32;
    int bh = blockIdx.z;
    int b = bh >> 4, h = bh & 15;
    int tx = threadIdx.x, ty = threadIdx.y;  // (32, 8)
    #pragma unroll
    for (int r = 0; r < 32; r += 8)
        tile[ty + r][tx] = qkv[(size_t)(b * SEQ + t0 + ty + r) * C3 + 2 * CDIM + h * HDIM + d0 + tx];
    __syncthreads();
    #pragma unroll
    for (int r = 0; r < 32; r += 8) {
        int d = d0 + ty + r;
        int t = t0 + tx;
        float v = tile[tx][ty + r];
        __nv_bfloat16 hi = __float2bfloat16(v);
        __nv_bfloat16 lo = __float2bfloat16(v - __bfloat162float(hi));
        size_t base = (((size_t)bh * HDIM + d) * 2) * SEQ + t;
        vt[base]       = hi;
        vt[base + SEQ] = lo;
    }
}

// ---------------------------------------------------------------------------
// Tensor-core flash attention, split-bf16, causal, ldsm-deduplicated:
// each physical fragment (Q/K/V hi and lo) is loaded ONCE per kt and reused
// across the 3 split planes (Qhi·Khi + Qhi·Klo + Qlo·Khi; Phi·Vhi + Phi·Vlo
// + Plo·Vhi). 80 ldsm per warp-kt (was 120) -> mma-bound.
// ---------------------------------------------------------------------------
#define FA_SMEM (32768 + 2 * 32768 + 128)

__global__ __launch_bounds__(128, 2)
void flash_mma_kernel(const __nv_bfloat16* __restrict__ qs,
                      const __nv_bfloat16* __restrict__ ks,
                      const __nv_bfloat16* __restrict__ vt,
                      float* __restrict__ Y) {
    extern __shared__ char smraw[];
    uint32_t smQ = (smem_u32(smraw) + 127u) & ~127u;

    int tid  = threadIdx.x;
    int wid  = tid >> 5, lane = tid & 31;
    int qt   = gridDim.x - 1 - blockIdx.x;   // heavy first
    int bh   = blockIdx.y;
    int q0   = qt * 64;
    int b = bh >> 4, h = bh & 15;

    const __nv_bfloat16* Qg = qs + ((size_t)bh * SEQ + q0) * 256;
    #pragma unroll
    for (int j = 0; j < 16; j++) {
        int ch = j * 128 + tid;
        int row = ch >> 5, c16 = ch & 31;
        uint32_t dst = smQ + (uint32_t)row * 512u + (uint32_t)((c16 ^ (row & 7)) << 4);
        CP_ASYNC16(dst, Qg + (size_t)row * 256 + c16 * 8);
    }

    auto fillKV = [&](int s, int kt) {
        int k0 = kt * 32;
        uint32_t smK = smQ + 32768u + (uint32_t)s * 32768u;
        uint32_t smV = smK + 16384u;
        const __nv_bfloat16* Kg = ks + ((size_t)bh * SEQ + k0) * 256;
        #pragma unroll
        for (int j = 0; j < 8; j++) {
            int ch = j * 128 + tid;
            int row = ch >> 5, c16 = ch & 31;
            uint32_t dst = smK + (uint32_t)row * 512u + (uint32_t)((c16 ^ (row & 7)) << 4);
            CP_ASYNC16(dst, Kg + (size_t)row * 256 + c16 * 8);
        }
        const __nv_bfloat16* Vg = vt + (size_t)bh * HDIM * 2 * SEQ + k0;
        #pragma unroll
        for (int j = 0; j < 8; j++) {
            int ch = j * 128 + tid;
            int row = ch >> 3, c16 = ch & 7;
            int plane = c16 >> 2, tc = c16 & 3;
            uint32_t dst = smV + (uint32_t)row * 128u + (uint32_t)((c16 ^ (row & 7)) << 4);
            CP_ASYNC16(dst, Vg + ((size_t)row * 2 + plane) * SEQ + tc * 8);
        }
    };

    fillKV(0, 0);
    CP_COMMIT();

    float O[16][4];
    #pragma unroll
    for (int nf = 0; nf < 16; nf++)
        #pragma unroll
        for (int c = 0; c < 4; c++) O[nf][c] = 0.f;
    float mrow[2] = { -1e30f, -1e30f };
    float lrow[2] = { 0.f, 0.f };

    int arow = wid * 16 + (lane & 15);
    uint32_t a_base = (uint32_t)arow * 512u;
    uint32_t a_x7   = (uint32_t)(arow & 7) << 4;
    uint32_t a_kb   = (uint32_t)((lane >> 4) << 4);
    int b_sub = ((lane >> 4) << 3) + (lane & 7);
    uint32_t b_kb = (uint32_t)(((lane >> 3) & 1) << 4);

    int nkt = 2 * qt + 2;
    for (int kt = 0; kt < nkt; kt++) {
        if (kt + 1 < nkt) { fillKV((kt + 1) & 1, kt + 1); CP_COMMIT(); CP_WAIT(1); }
        else              { CP_WAIT(0); }
        __syncthreads();

        uint32_t smK = smQ + 32768u + (uint32_t)(kt & 1) * 32768u;
        uint32_t smV = smK + 16384u;

        // ---- S: load Qhi,Qlo,Khi,Klo once per kd; 12 mma per kd ----
        float S[4][4];
        #pragma unroll
        for (int ni = 0; ni < 4; ni++)
            #pragma unroll
            for (int c = 0; c < 4; c++) S[ni][c] = 0.f;

        #pragma unroll
        for (int kd = 0; kd < 8; kd++) {
            uint32_t aH[4], aL[4];
            ldsm_x4(aH[0], aH[1], aH[2], aH[3],
                    smQ + a_base + ((        kd * 32 + a_kb) ^ a_x7));
            ldsm_x4(aL[0], aL[1], aL[2], aL[3],
                    smQ + a_base + ((256u +  kd * 32 + a_kb) ^ a_x7));
            #pragma unroll
            for (int g = 0; g < 2; g++) {
                int brow = g * 16 + b_sub;
                uint32_t bx7 = (uint32_t)(brow & 7) << 4;
                uint32_t bH[4], bL[4];
                ldsm_x4(bH[0], bH[1], bH[2], bH[3],
                        smK + (uint32_t)brow * 512u + ((        kd * 32 + b_kb) ^ bx7));
                ldsm_x4(bL[0], bL[1], bL[2], bL[3],
                        smK + (uint32_t)brow * 512u + ((256u +  kd * 32 + b_kb) ^ bx7));
                #pragma unroll
                for (int sub = 0; sub < 2; sub++) {
                    int ni = g * 2 + sub;
                    mma_bf16(S[ni][0], S[ni][1], S[ni][2], S[ni][3],
                             aH[0], aH[1], aH[2], aH[3], bH[sub*2], bH[sub*2+1]);
                    mma_bf16(S[ni][0], S[ni][1], S[ni][2], S[ni][3],
                             aH[0], aH[1], aH[2], aH[3], bL[sub*2], bL[sub*2+1]);
                    mma_bf16(S[ni][0], S[ni][1], S[ni][2], S[ni][3],
                             aL[0], aL[1], aL[2], aL[3], bH[sub*2], bH[sub*2+1]);
                }
            }
        }

        if (kt >= 2 * qt) {
            int k0 = kt * 32;
            #pragma unroll
            for (int ni = 0; ni < 4; ni++) {
                #pragma unroll
                for (int c = 0; c < 4; c++) {
                    int gr = q0 + wid * 16 + (lane >> 2) + ((c >> 1) << 3);
                    int gc = k0 + ni * 8 + (lane & 3) * 2 + (c & 1);
                    if (gc > gr) S[ni][c] = -1e30f;
                }
            }
        }

        // ---- online softmax ----
        uint32_t phi[2][4], plo[2][4];
        #pragma unroll
        for (int i = 0; i < 2; i++) {
            float vmax = -1e30f;
            #pragma unroll
            for (int ni = 0; ni < 4; ni++)
                vmax = fmaxf(vmax, fmaxf(S[ni][2*i], S[ni][2*i+1]));
            vmax = fmaxf(vmax, __shfl_xor_sync(0xffffffffu, vmax, 1));
            vmax = fmaxf(vmax, __shfl_xor_sync(0xffffffffu, vmax, 2));
            float mnew  = fmaxf(mrow[i], vmax);
            float alpha = __expf(mrow[i] - mnew);
            mrow[i] = mnew;
            float rs = 0.f;
            #pragma unroll
            for (int ni = 0; ni < 4; ni++) {
                float p0 = __expf(S[ni][2*i]   - mnew);
                float p1 = __expf(S[ni][2*i+1] - mnew);
                S[ni][2*i] = p0; S[ni][2*i+1] = p1;
                rs += p0 + p1;
            }
            rs += __shfl_xor_sync(0xffffffffu, rs, 1);
            rs += __shfl_xor_sync(0xffffffffu, rs, 2);
            lrow[i] = lrow[i] * alpha + rs;
            #pragma unroll
            for (int nf = 0; nf < 16; nf++) {
                O[nf][2*i]   *= alpha;
                O[nf][2*i+1] *= alpha;
            }
        }
        #pragma unroll
        for (int ks2 = 0; ks2 < 2; ks2++) {
            #pragma unroll
            for (int half = 0; half < 2; half++) {
                int ni = 2 * ks2 + half;
                float p00 = S[ni][0], p01 = S[ni][1], p10 = S[ni][2], p11 = S[ni][3];
                __nv_bfloat16 h00 = __float2bfloat16(p00), h01 = __float2bfloat16(p01);
                __nv_bfloat16 h10 = __float2bfloat16(p10), h11 = __float2bfloat16(p11);
                phi[ks2][half*2+0] = pack_bf16(__bfloat162float(h00), __bfloat162float(h01));
                phi[ks2][half*2+1] = pack_bf16(__bfloat162float(h10), __bfloat162float(h11));
                plo[ks2][half*2+0] = pack_bf16(p00 - __bfloat162float(h00),
                                               p01 - __bfloat162float(h01));
                plo[ks2][half*2+1] = pack_bf16(p10 - __bfloat162float(h10),
                                               p11 - __bfloat162float(h11));
            }
        }

        // ---- O: load Vhi,Vlo once per (ks2,nb); 6 mma per pair ----
        #pragma unroll
        for (int ks2 = 0; ks2 < 2; ks2++) {
            #pragma unroll
            for (int nb = 0; nb < 8; nb++) {
                int brow = nb * 16 + b_sub;
                uint32_t bx7 = (uint32_t)(brow & 7) << 4;
                uint32_t bvH[4], bvL[4];
                ldsm_x4(bvH[0], bvH[1], bvH[2], bvH[3],
                        smV + (uint32_t)brow * 128u + ((       ks2 * 32 + b_kb) ^ bx7));
                ldsm_x4(bvL[0], bvL[1], bvL[2], bvL[3],
                        smV + (uint32_t)brow * 128u + ((64u +  ks2 * 32 + b_kb) ^ bx7));
                #pragma unroll
                for (int sub = 0; sub < 2; sub++) {
                    int nf = nb * 2 + sub;
                    mma_bf16(O[nf][0], O[nf][1], O[nf][2], O[nf][3],
                             phi[ks2][0], phi[ks2][1], phi[ks2][2], phi[ks2][3],
                             bvH[sub*2], bvH[sub*2+1]);
                    mma_bf16(O[nf][0], O[nf][1], O[nf][2], O[nf][3],
                             phi[ks2][0], phi[ks2][1], phi[ks2][2], phi[ks2][3],
                             bvL[sub*2], bvL[sub*2+1]);
                    mma_bf16(O[nf][0], O[nf][1], O[nf][2], O[nf][3],
                             plo[ks2][0], plo[ks2][1], plo[ks2][2], plo[ks2][3],
                             bvH[sub*2], bvH[sub*2+1]);
                }
            }
        }
        __syncthreads();
    }

    #pragma unroll
    for (int i = 0; i < 2; i++) {
        float inv = 1.0f / lrow[i];
        int trow = q0 + wid * 16 + (lane >> 2) + 8 * i;
        float* yr = Y + (size_t)(b * SEQ + trow) * CDIM + h * HDIM + (lane & 3) * 2;
        #pragma unroll
        for (int nf = 0; nf < 16; nf++) {
            float2 v = { O[nf][2*i] * inv, O[nf][2*i+1] * inv };
            *(float2*)(yr + nf * 8) = v;
        }
    }
}

// ---------------------------------------------------------------------------
extern "C" void kernel_launch(void* const* d_in, const int* in_sizes, int n_in,
                              void* d_out, int out_size) {
    const float* x      = (const float*)d_in[0];
    const float* w_attn = (const float*)d_in[1];
    const float* b_attn = (const float*)d_in[2];
    const float* w_proj = (const float*)d_in[3];
    const float* b_proj = (const float*)d_in[4];
    float* out = (float*)d_out;

    float *qkv, *y, *ct, *st;
    __nv_bfloat16 *Abuf, *Bt1, *Bt2, *qsb, *ksb, *vtb;
    cudaGetSymbolAddress((void**)&qkv,  g_qkv);
    cudaGetSymbolAddress((void**)&y,    g_y);
    cudaGetSymbolAddress((void**)&ct,   g_cos);
    cudaGetSymbolAddress((void**)&st,   g_sin);
    cudaGetSymbolAddress((void**)&Abuf, g_Abuf);
    cudaGetSymbolAddress((void**)&Bt1,  g_Bt1);
    cudaGetSymbolAddress((void**)&Bt2,  g_Bt2);
    cudaGetSymbolAddress((void**)&qsb,  g_qs);
    cudaGetSymbolAddress((void**)&ksb,  g_ks);
    cudaGetSymbolAddress((void**)&vtb,  g_vt);

    cudaFuncSetAttribute(mma_gemm_kernel,
                         cudaFuncAttributeMaxDynamicSharedMemorySize, GEMM_SMEM);
    cudaFuncSetAttribute(flash_mma_kernel,
                         cudaFuncAttributeMaxDynamicSharedMemorySize, FA_SMEM);

    // RoPE tables
    build_rope_kernel<<<(SEQ * 64 + 255) / 256, 256>>>(ct, st);

    // Split-bf16 conversions for QKV GEMM
    convert_A_kernel<<<(MROWS * CDIM / 4 + 255) / 256, 256>>>(x, Abuf);
    convert_Bt_kernel<<<dim3(CDIM / 32, C3 / 32), dim3(32, 8)>>>(w_attn, Bt1, C3);

    // QKV projection (HMMA)
    mma_gemm_kernel<<<dim3(C3 / 128, MROWS / 128), 128, GEMM_SMEM>>>(
        Abuf, Bt1, b_attn, qkv, C3);

    // RoPE + split into bf16 hi/lo; V transpose + split
    rope_split_kernel<<<(BHTOT * SEQ * HDIM + 255) / 256, 256>>>(qkv, ct, st, qsb, ksb);
    vt_split_kernel<<<dim3(SEQ / 32, HDIM / 32, BHTOT), dim3(32, 8)>>>(qkv, vtb);

    // Tensor-core flash attention -> y
    flash_mma_kernel<<<dim3(SEQ / 64, BHTOT), 128, FA_SMEM>>>(qsb, ksb, vtb, y);

    // Split-bf16 conversions for output projection
    convert_A_kernel<<<(MROWS * CDIM / 4 + 255) / 256, 256>>>(y, Abuf);
    convert_Bt_kernel<<<dim3(CDIM / 32, CDIM / 32), dim3(32, 8)>>>(w_proj, Bt2, CDIM);

    // Output projection (HMMA) -> d_out
    mma_gemm_kernel<<<dim3(CDIM / 128, MROWS / 128), 128, GEMM_SMEM>>>(
        Abuf, Bt2, b_proj, out, CDIM);
}